// round 13
// baseline (speedup 1.0000x reference)
#include <cuda_runtime.h>
#include <cuda_fp16.h>
#include <stdint.h>

#define BH      32
#define SEQ     2048
#define DMV     128
#define DS      16
#define DTOT    144
#define BM      128
#define BN      64
#define NTILES  (SEQ / BN)
#define NTHREADS 256

// Row stride 76 words = 304B: 16B-aligned, 19 bank-quads (odd -> conflict-free ldmatrix)
#define QW     76
#define KPL    (BN * QW)            // one K/V plane: 4864 words
#define O_QH   0
#define O_QL   (O_QH + BM * QW)     // 9728
#define O_K0   (O_QL + BM * QW)     // 19456 (hi only, double-buffered)
#define O_K1   (O_K0 + KPL)         // 24320
#define O_V0   (O_K1 + KPL)         // 29184 (hi only, double-buffered)
#define O_V1   (O_V0 + KPL)         // 34048
#define SMEM_WORDS (O_V1 + KPL)     // 38912 words = 155648 B

// sign pattern: -1 at indices {2..7,14,15} (mod 16)
#define NEGMASK 0xC0FCu

static __device__ __forceinline__ uint32_t smem_u32(const void* p) {
    uint32_t a;
    asm("{ .reg .u64 t; cvta.to.shared.u64 t, %1; cvt.u32.u64 %0, t; }" : "=r"(a) : "l"(p));
    return a;
}

static __device__ __forceinline__ uint32_t pack_split(float x0, float x1, uint32_t& lop) {
    __half h0 = __float2half_rn(x0);
    __half h1 = __float2half_rn(x1);
    float r0 = x0 - __half2float(h0);
    float r1 = x1 - __half2float(h1);
    __half l0 = __float2half_rn(r0);
    __half l1 = __float2half_rn(r1);
    lop = (uint32_t)__half_as_ushort(l0) | ((uint32_t)__half_as_ushort(l1) << 16);
    return (uint32_t)__half_as_ushort(h0) | ((uint32_t)__half_as_ushort(h1) << 16);
}

static __device__ __forceinline__ uint32_t pack_hi(float x0, float x1) {
    __half2 h = __floats2half2_rn(x0, x1);
    return *(const uint32_t*)&h;
}

static __device__ __forceinline__ float ex2f(float x) {
    float r;
    asm("ex2.approx.f32 %0, %1;" : "=f"(r) : "f"(x));
    return r;
}

static __device__ __forceinline__ void mma16816(float* d, const uint32_t* a,
                                                uint32_t b0, uint32_t b1) {
    asm volatile(
        "mma.sync.aligned.m16n8k16.row.col.f32.f16.f16.f32 "
        "{%0,%1,%2,%3}, {%4,%5,%6,%7}, {%8,%9}, {%0,%1,%2,%3};"
        : "+f"(d[0]), "+f"(d[1]), "+f"(d[2]), "+f"(d[3])
        : "r"(a[0]), "r"(a[1]), "r"(a[2]), "r"(a[3]), "r"(b0), "r"(b1));
}

static __device__ __forceinline__ void ldm4(uint32_t* r, uint32_t saddr) {
    asm volatile("ldmatrix.sync.aligned.m8n8.x4.shared.b16 {%0,%1,%2,%3}, [%4];"
        : "=r"(r[0]), "=r"(r[1]), "=r"(r[2]), "=r"(r[3]) : "r"(saddr));
}

static __device__ __forceinline__ void ldm4t(uint32_t* r, uint32_t saddr) {
    asm volatile("ldmatrix.sync.aligned.m8n8.x4.trans.shared.b16 {%0,%1,%2,%3}, [%4];"
        : "=r"(r[0]), "=r"(r[1]), "=r"(r[2]), "=r"(r[3]) : "r"(saddr));
}

__global__ __launch_bounds__(NTHREADS, 1)
void geo_attn_hmma(const float* __restrict__ q_mv, const float* __restrict__ k_mv,
                   const float* __restrict__ v_mv, const float* __restrict__ q_s,
                   const float* __restrict__ k_s,  const float* __restrict__ v_s,
                   float* __restrict__ out)
{
    extern __shared__ uint32_t smw[];
    const uint32_t sb = smem_u32(smw);

    const int tid  = threadIdx.x;
    const int lane = tid & 31;
    const int wid  = tid >> 5;
    const int quad = lane >> 2;
    const int mrow = wid * 16;
    const int bh   = blockIdx.y;
    const int i0   = blockIdx.x * BM;

    const int l8  = lane & 7;
    const int lb3 = (lane >> 3) & 1;
    const int lb4 = (lane >> 4) & 1;
    const uint32_t qa_base = sb + 4u * (O_QH + (uint32_t)(mrow + lb3 * 8 + l8) * QW + lb4 * 4);
    const uint32_t kb_lane = 4u * ((uint32_t)(lb4 * 8 + l8) * QW + lb3 * 4);  // K (non-trans B)
    const uint32_t vb_lane = 4u * ((uint32_t)(lb3 * 8 + l8) * QW + lb4 * 4);  // V (trans B)

    // scale folded with log2(e): softmax becomes bare ex2
    const float SCALE = 0.120224586740747f;   // log2(e)/12

    // ---------------- Q: gmem -> SMEM fp16 hi/lo (signed + scaled) ----------------
    {
        const float2* qmv2 = (const float2*)(q_mv + (size_t)(bh * SEQ + i0) * DMV);
        const float2* qs2  = (const float2*)(q_s  + (size_t)(bh * SEQ + i0) * DS);
        #pragma unroll
        for (int it = 0; it < 32; ++it) {
            int idx = it * NTHREADS + tid;
            int r = idx >> 6, w = idx & 63;
            float2 f = qmv2[r * 64 + w];
            uint32_t fx = __float_as_uint(f.x) ^ (((NEGMASK >> ((2 * w) & 15)) & 1u) << 31);
            uint32_t fy = __float_as_uint(f.y) ^ (((NEGMASK >> ((2 * w + 1) & 15)) & 1u) << 31);
            uint32_t lo, hi = pack_split(__uint_as_float(fx) * SCALE,
                                         __uint_as_float(fy) * SCALE, lo);
            smw[O_QH + r * QW + w] = hi;
            smw[O_QL + r * QW + w] = lo;
        }
        #pragma unroll
        for (int it = 0; it < 4; ++it) {
            int idx = it * NTHREADS + tid;
            int r = idx >> 3, w = idx & 7;
            float2 f = qs2[r * 8 + w];
            uint32_t lo, hi = pack_split(f.x * SCALE, f.y * SCALE, lo);
            smw[O_QH + r * QW + 64 + w] = hi;
            smw[O_QL + r * QW + 64 + w] = lo;
        }
    }

    // ---------------- Prologue: K/V tile 0 -> buffer 0 (hi only) ----------------
    {
        const float2* kmv2 = (const float2*)(k_mv + (size_t)(bh * SEQ) * DMV);
        const float2* ks2  = (const float2*)(k_s  + (size_t)(bh * SEQ) * DS);
        const float2* vmv2 = (const float2*)(v_mv + (size_t)(bh * SEQ) * DMV);
        const float2* vs2  = (const float2*)(v_s  + (size_t)(bh * SEQ) * DS);
        #pragma unroll
        for (int it = 0; it < 16; ++it) {
            int idx = it * NTHREADS + tid;
            int r = idx >> 6, w = idx & 63;
            float2 fk = kmv2[r * 64 + w];
            smw[O_K0 + r * QW + w] = pack_hi(fk.x, fk.y);
            float2 fv = vmv2[r * 64 + w];
            smw[O_V0 + r * QW + w] = pack_hi(fv.x, fv.y);
        }
        #pragma unroll
        for (int it = 0; it < 2; ++it) {
            int idx = it * NTHREADS + tid;
            int r = idx >> 3, w = idx & 7;
            float2 fk = ks2[r * 8 + w];
            smw[O_K0 + r * QW + 64 + w] = pack_hi(fk.x, fk.y);
            float2 fv = vs2[r * 8 + w];
            smw[O_V0 + r * QW + 64 + w] = pack_hi(fv.x, fv.y);
        }
    }
    __syncthreads();

    float oacc[18][4];
    #pragma unroll
    for (int j = 0; j < 18; ++j)
        #pragma unroll
        for (int r = 0; r < 4; ++r) oacc[j][r] = 0.0f;
    float rs0a = 0.0f, rs1a = 0.0f;

    for (int t = 0; t < NTILES; ++t) {
        const int buf = t & 1;
        const uint32_t kbase = sb + 4u * (uint32_t)(O_K0 + buf * KPL);
        const uint32_t vbase = sb + 4u * (uint32_t)(O_V0 + buf * KPL);
        const int nK = O_K0 + (buf ^ 1) * KPL;
        const int nV = O_V0 + (buf ^ 1) * KPL;
        const int tn = (t + 1) & (NTILES - 1);

        // ---- S = Q K^T (2-term: (Qh+Ql) x Kh) ----
        float sacc[8][4];
        #pragma unroll
        for (int j = 0; j < 8; ++j)
            #pragma unroll
            for (int r = 0; r < 4; ++r) sacc[j][r] = 0.0f;

        #pragma unroll 1
        for (int c = 0; c < 9; ++c) {
            uint32_t ah[4], al[4];
            const uint32_t qa = qa_base + (uint32_t)c * 32u;
            ldm4(ah, qa);
            ldm4(al, qa + 4u * (uint32_t)(O_QL - O_QH));
            #pragma unroll
            for (int jp = 0; jp < 4; ++jp) {
                uint32_t kh[4];
                const uint32_t ka = kbase + (uint32_t)jp * (16u * QW * 4u)
                                  + (uint32_t)c * 32u + kb_lane;
                ldm4(kh, ka);
                mma16816(sacc[2*jp],   ah, kh[0], kh[1]);
                mma16816(sacc[2*jp+1], ah, kh[2], kh[3]);
                mma16816(sacc[2*jp],   al, kh[0], kh[1]);
                mma16816(sacc[2*jp+1], al, kh[2], kh[3]);
            }
        }

        // ---- issue K(t+1) global loads (latency hidden by softmax) ----
        float2 kreg[18];
        {
            const float2* kmv2 = (const float2*)(k_mv + (size_t)(bh * SEQ + tn * BN) * DMV);
            const float2* ks2  = (const float2*)(k_s  + (size_t)(bh * SEQ + tn * BN) * DS);
            #pragma unroll
            for (int it = 0; it < 16; ++it) {
                int idx = it * NTHREADS + tid;
                kreg[it] = kmv2[(idx >> 6) * 64 + (idx & 63)];
            }
            #pragma unroll
            for (int it = 0; it < 2; ++it) {
                int idx = it * NTHREADS + tid;
                kreg[16 + it] = ks2[(idx >> 3) * 8 + (idx & 7)];
            }
        }

        // ---- softmax in log2 domain (scores pre-scaled by log2e/12) ----
        uint32_t Ph[4][4], Pl[4][4];
        float rst0 = 0.0f, rst1 = 0.0f;
        #pragma unroll
        for (int j = 0; j < 8; ++j) {
            float e0 = ex2f(sacc[j][0]);
            float e1 = ex2f(sacc[j][1]);
            float e2 = ex2f(sacc[j][2]);
            float e3 = ex2f(sacc[j][3]);
            rst0 += e0 + e1;
            rst1 += e2 + e3;
            const int kc = j >> 1, hh = (j & 1) * 2;
            Ph[kc][hh + 0] = pack_split(e0, e1, Pl[kc][hh + 0]);
            Ph[kc][hh + 1] = pack_split(e2, e3, Pl[kc][hh + 1]);
        }
        rst0 += __shfl_xor_sync(0xffffffffu, rst0, 1);
        rst0 += __shfl_xor_sync(0xffffffffu, rst0, 2);
        rst1 += __shfl_xor_sync(0xffffffffu, rst1, 1);
        rst1 += __shfl_xor_sync(0xffffffffu, rst1, 2);
        rs0a += rst0;
        rs1a += rst1;

        // ---- convert+store K(t+1) (hi only) ----
        #pragma unroll
        for (int it = 0; it < 16; ++it) {
            int idx = it * NTHREADS + tid;
            int r = idx >> 6, w = idx & 63;
            smw[nK + r * QW + w] = pack_hi(kreg[it].x, kreg[it].y);
        }
        #pragma unroll
        for (int it = 0; it < 2; ++it) {
            int idx = it * NTHREADS + tid;
            int r = idx >> 3, w = idx & 7;
            smw[nK + r * QW + 64 + w] = pack_hi(kreg[16 + it].x, kreg[16 + it].y);
        }

        // ---- issue V(t+1) global loads (latency hidden by PV) ----
        float2 vreg[18];
        {
            const float2* vmv2 = (const float2*)(v_mv + (size_t)(bh * SEQ + tn * BN) * DMV);
            const float2* vs2  = (const float2*)(v_s  + (size_t)(bh * SEQ + tn * BN) * DS);
            #pragma unroll
            for (int it = 0; it < 16; ++it) {
                int idx = it * NTHREADS + tid;
                vreg[it] = vmv2[(idx >> 6) * 64 + (idx & 63)];
            }
            #pragma unroll
            for (int it = 0; it < 2; ++it) {
                int idx = it * NTHREADS + tid;
                vreg[16 + it] = vs2[(idx >> 3) * 8 + (idx & 7)];
            }
        }

        // ---- O += P V (2-term: (Ph+Pl) x Vh), V B-frags via ldmatrix.trans ----
        #pragma unroll 1
        for (int jp = 0; jp < 9; ++jp) {
            #pragma unroll
            for (int kc = 0; kc < 4; ++kc) {
                uint32_t vh[4];
                const uint32_t va = vbase + vb_lane
                                  + 4u * ((uint32_t)kc * 16u * QW + (uint32_t)jp * 8u);
                ldm4t(vh, va);
                mma16816(oacc[2*jp],   Ph[kc], vh[0], vh[1]);
                mma16816(oacc[2*jp+1], Ph[kc], vh[2], vh[3]);
                mma16816(oacc[2*jp],   Pl[kc], vh[0], vh[1]);
                mma16816(oacc[2*jp+1], Pl[kc], vh[2], vh[3]);
            }
        }

        // ---- convert+store V(t+1) ----
        #pragma unroll
        for (int it = 0; it < 16; ++it) {
            int idx = it * NTHREADS + tid;
            int r = idx >> 6, w = idx & 63;
            smw[nV + r * QW + w] = pack_hi(vreg[it].x, vreg[it].y);
        }
        #pragma unroll
        for (int it = 0; it < 2; ++it) {
            int idx = it * NTHREADS + tid;
            int r = idx >> 3, w = idx & 7;
            smw[nV + r * QW + 64 + w] = pack_hi(vreg[16 + it].x, vreg[16 + it].y);
        }

        __syncthreads();
    }

    // ---------------- Epilogue: normalize + write ----------------
    {
        const int q4 = lane & 3;
        const float inv0 = 1.0f / rs0a;
        const float inv1 = 1.0f / rs1a;
        const size_t g0 = (size_t)(bh * SEQ + i0 + mrow + quad);
        const size_t g1 = g0 + 8;
        float* out_s = out + (size_t)BH * SEQ * DMV;
        #pragma unroll
        for (int j2 = 0; j2 < 18; ++j2) {
            const int col = j2 * 8 + q4 * 2;
            float2 r0 = make_float2(oacc[j2][0] * inv0, oacc[j2][1] * inv0);
            float2 r1 = make_float2(oacc[j2][2] * inv1, oacc[j2][3] * inv1);
            if (col < DMV) {
                *(float2*)(out + g0 * DMV + col) = r0;
                *(float2*)(out + g1 * DMV + col) = r1;
            } else {
                *(float2*)(out_s + g0 * DS + (col - DMV)) = r0;
                *(float2*)(out_s + g1 * DS + (col - DMV)) = r1;
            }
        }
    }
}

extern "C" void kernel_launch(void* const* d_in, const int* in_sizes, int n_in,
                              void* d_out, int out_size)
{
    (void)in_sizes; (void)n_in; (void)out_size;
    const float* q_mv = (const float*)d_in[0];
    const float* k_mv = (const float*)d_in[1];
    const float* v_mv = (const float*)d_in[2];
    const float* q_s  = (const float*)d_in[3];
    const float* k_s  = (const float*)d_in[4];
    const float* v_s  = (const float*)d_in[5];
    float* out = (float*)d_out;

    const int smem_bytes = SMEM_WORDS * 4;
    cudaFuncSetAttribute(geo_attn_hmma,
                         cudaFuncAttributeMaxDynamicSharedMemorySize, smem_bytes);
    dim3 grid(SEQ / BM, BH);
    geo_attn_hmma<<<grid, NTHREADS, smem_bytes>>>(q_mv, k_mv, v_mv, q_s, k_s, v_s, out);
}

// round 14
// speedup vs baseline: 1.1693x; 1.1693x over previous
#include <cuda_runtime.h>
#include <cuda_fp16.h>
#include <stdint.h>

#define BH      32
#define SEQ     2048
#define DMV     128
#define DS      16
#define DTOT    144
#define BM      128
#define BN      64
#define NTILES  (SEQ / BN)
#define NTHREADS 256

// Row stride 76 words = 304B: 16B-aligned, 19 bank-quads (odd -> conflict-free ldmatrix)
#define QW     76
#define KPL    (BN * QW)            // one K/V plane: 4864 words
#define O_QH   0
#define O_QL   (O_QH + BM * QW)     // 9728
#define O_K0   (O_QL + BM * QW)     // 19456 (hi plane; lo at +KPL)
#define O_K1   (O_K0 + 2 * KPL)     // 29184
#define O_V0   (O_K1 + 2 * KPL)     // 38912 (hi only)
#define O_V1   (O_V0 + KPL)         // 43776
#define SMEM_WORDS (O_V1 + KPL)     // 48640 words = 194560 B

// sign pattern: -1 at indices {2..7,14,15} (mod 16)
#define NEGMASK 0xC0FCu

static __device__ __forceinline__ uint32_t smem_u32(const void* p) {
    uint32_t a;
    asm("{ .reg .u64 t; cvta.to.shared.u64 t, %1; cvt.u32.u64 %0, t; }" : "=r"(a) : "l"(p));
    return a;
}

static __device__ __forceinline__ uint32_t pack_split(float x0, float x1, uint32_t& lop) {
    __half h0 = __float2half_rn(x0);
    __half h1 = __float2half_rn(x1);
    float r0 = x0 - __half2float(h0);
    float r1 = x1 - __half2float(h1);
    __half l0 = __float2half_rn(r0);
    __half l1 = __float2half_rn(r1);
    lop = (uint32_t)__half_as_ushort(l0) | ((uint32_t)__half_as_ushort(l1) << 16);
    return (uint32_t)__half_as_ushort(h0) | ((uint32_t)__half_as_ushort(h1) << 16);
}

static __device__ __forceinline__ uint32_t pack_hi(float x0, float x1) {
    __half2 h = __floats2half2_rn(x0, x1);
    return *(const uint32_t*)&h;
}

static __device__ __forceinline__ float ex2f(float x) {
    float r;
    asm("ex2.approx.f32 %0, %1;" : "=f"(r) : "f"(x));
    return r;
}

static __device__ __forceinline__ void mma16816(float* d, const uint32_t* a,
                                                uint32_t b0, uint32_t b1) {
    asm volatile(
        "mma.sync.aligned.m16n8k16.row.col.f32.f16.f16.f32 "
        "{%0,%1,%2,%3}, {%4,%5,%6,%7}, {%8,%9}, {%0,%1,%2,%3};"
        : "+f"(d[0]), "+f"(d[1]), "+f"(d[2]), "+f"(d[3])
        : "r"(a[0]), "r"(a[1]), "r"(a[2]), "r"(a[3]), "r"(b0), "r"(b1));
}

static __device__ __forceinline__ void ldm4(uint32_t* r, uint32_t saddr) {
    asm volatile("ldmatrix.sync.aligned.m8n8.x4.shared.b16 {%0,%1,%2,%3}, [%4];"
        : "=r"(r[0]), "=r"(r[1]), "=r"(r[2]), "=r"(r[3]) : "r"(saddr));
}

static __device__ __forceinline__ void ldm4t(uint32_t* r, uint32_t saddr) {
    asm volatile("ldmatrix.sync.aligned.m8n8.x4.trans.shared.b16 {%0,%1,%2,%3}, [%4];"
        : "=r"(r[0]), "=r"(r[1]), "=r"(r[2]), "=r"(r[3]) : "r"(saddr));
}

__global__ __launch_bounds__(NTHREADS, 1)
void geo_attn_hmma(const float* __restrict__ q_mv, const float* __restrict__ k_mv,
                   const float* __restrict__ v_mv, const float* __restrict__ q_s,
                   const float* __restrict__ k_s,  const float* __restrict__ v_s,
                   float* __restrict__ out)
{
    extern __shared__ uint32_t smw[];
    const uint32_t sb = smem_u32(smw);

    const int tid  = threadIdx.x;
    const int lane = tid & 31;
    const int wid  = tid >> 5;
    const int quad = lane >> 2;
    const int mrow = wid * 16;
    const int bh   = blockIdx.y;
    const int i0   = blockIdx.x * BM;

    const int l8  = lane & 7;
    const int lb3 = (lane >> 3) & 1;
    const int lb4 = (lane >> 4) & 1;
    const uint32_t qa_base = sb + 4u * (O_QH + (uint32_t)(mrow + lb3 * 8 + l8) * QW + lb4 * 4);
    const uint32_t kb_lane = 4u * ((uint32_t)(lb4 * 8 + l8) * QW + lb3 * 4);  // K (non-trans B)
    const uint32_t vb_lane = 4u * ((uint32_t)(lb3 * 8 + l8) * QW + lb4 * 4);  // V (trans B)

    // log2(e)/12 folded into Q so softmax is bare ex2
    const float SCALE = 0.120224586740747f;

    // ---------------- Q: gmem -> SMEM fp16 hi/lo (signed + scaled) ----------------
    {
        const float2* qmv2 = (const float2*)(q_mv + (size_t)(bh * SEQ + i0) * DMV);
        const float2* qs2  = (const float2*)(q_s  + (size_t)(bh * SEQ + i0) * DS);
        #pragma unroll
        for (int it = 0; it < 32; ++it) {
            int idx = it * NTHREADS + tid;
            int r = idx >> 6, w = idx & 63;
            float2 f = qmv2[r * 64 + w];
            uint32_t fx = __float_as_uint(f.x) ^ (((NEGMASK >> ((2 * w) & 15)) & 1u) << 31);
            uint32_t fy = __float_as_uint(f.y) ^ (((NEGMASK >> ((2 * w + 1) & 15)) & 1u) << 31);
            uint32_t lo, hi = pack_split(__uint_as_float(fx) * SCALE,
                                         __uint_as_float(fy) * SCALE, lo);
            smw[O_QH + r * QW + w] = hi;
            smw[O_QL + r * QW + w] = lo;
        }
        #pragma unroll
        for (int it = 0; it < 4; ++it) {
            int idx = it * NTHREADS + tid;
            int r = idx >> 3, w = idx & 7;
            float2 f = qs2[r * 8 + w];
            uint32_t lo, hi = pack_split(f.x * SCALE, f.y * SCALE, lo);
            smw[O_QH + r * QW + 64 + w] = hi;
            smw[O_QL + r * QW + 64 + w] = lo;
        }
    }

    // ---------------- Prologue: K/V tile 0 -> buffer 0 ----------------
    {
        const float2* kmv2 = (const float2*)(k_mv + (size_t)(bh * SEQ) * DMV);
        const float2* ks2  = (const float2*)(k_s  + (size_t)(bh * SEQ) * DS);
        const float2* vmv2 = (const float2*)(v_mv + (size_t)(bh * SEQ) * DMV);
        const float2* vs2  = (const float2*)(v_s  + (size_t)(bh * SEQ) * DS);
        #pragma unroll
        for (int it = 0; it < 16; ++it) {
            int idx = it * NTHREADS + tid;
            int r = idx >> 6, w = idx & 63;
            float2 fk = kmv2[r * 64 + w];
            uint32_t lo, hi = pack_split(fk.x, fk.y, lo);
            smw[O_K0 + r * QW + w] = hi;
            smw[O_K0 + KPL + r * QW + w] = lo;
            float2 fv = vmv2[r * 64 + w];
            smw[O_V0 + r * QW + w] = pack_hi(fv.x, fv.y);
        }
        #pragma unroll
        for (int it = 0; it < 2; ++it) {
            int idx = it * NTHREADS + tid;
            int r = idx >> 3, w = idx & 7;
            float2 fk = ks2[r * 8 + w];
            uint32_t lo, hi = pack_split(fk.x, fk.y, lo);
            smw[O_K0 + r * QW + 64 + w] = hi;
            smw[O_K0 + KPL + r * QW + 64 + w] = lo;
            float2 fv = vs2[r * 8 + w];
            smw[O_V0 + r * QW + 64 + w] = pack_hi(fv.x, fv.y);
        }
    }
    __syncthreads();

    float oacc[18][4];
    #pragma unroll
    for (int j = 0; j < 18; ++j)
        #pragma unroll
        for (int r = 0; r < 4; ++r) oacc[j][r] = 0.0f;
    float rs0a = 0.0f, rs1a = 0.0f;

    for (int t = 0; t < NTILES; ++t) {
        const int buf = t & 1;
        const uint32_t kbase = sb + 4u * (uint32_t)(O_K0 + buf * (2 * KPL));
        const uint32_t vbase = sb + 4u * (uint32_t)(O_V0 + buf * KPL);
        const int nK = O_K0 + (buf ^ 1) * (2 * KPL);
        const int nV = O_V0 + (buf ^ 1) * KPL;
        const int tn = (t + 1) & (NTILES - 1);

        const float2* kmv2n = (const float2*)(k_mv + (size_t)(bh * SEQ + tn * BN) * DMV);
        const float2* ks2n  = (const float2*)(k_s  + (size_t)(bh * SEQ + tn * BN) * DS);
        const float2* vmv2n = (const float2*)(v_mv + (size_t)(bh * SEQ + tn * BN) * DMV);
        const float2* vs2n  = (const float2*)(v_s  + (size_t)(bh * SEQ + tn * BN) * DS);

        // ---- issue first half of K(t+1) loads (long window: whole S phase) ----
        float2 kregA[9];
        #pragma unroll
        for (int it = 0; it < 8; ++it) {
            int idx = it * NTHREADS + tid;
            kregA[it] = kmv2n[(idx >> 6) * 64 + (idx & 63)];
        }
        kregA[8] = ks2n[(tid >> 3) * 8 + (tid & 7)];

        // ---- S = Q K^T (3-term split) ----
        float sacc[8][4];
        #pragma unroll
        for (int j = 0; j < 8; ++j)
            #pragma unroll
            for (int r = 0; r < 4; ++r) sacc[j][r] = 0.0f;

        #pragma unroll 1
        for (int c = 0; c < 9; ++c) {
            uint32_t ah[4], al[4];
            const uint32_t qa = qa_base + (uint32_t)c * 32u;
            ldm4(ah, qa);
            ldm4(al, qa + 4u * (uint32_t)(O_QL - O_QH));
            #pragma unroll
            for (int jp = 0; jp < 4; ++jp) {
                uint32_t khf[4], klf[4];
                const uint32_t ka = kbase + (uint32_t)jp * (16u * QW * 4u)
                                  + (uint32_t)c * 32u + kb_lane;
                ldm4(khf, ka);
                ldm4(klf, ka + 4u * (uint32_t)KPL);
                mma16816(sacc[2*jp],   ah, khf[0], khf[1]);
                mma16816(sacc[2*jp+1], ah, khf[2], khf[3]);
                mma16816(sacc[2*jp],   ah, klf[0], klf[1]);
                mma16816(sacc[2*jp+1], ah, klf[2], klf[3]);
                mma16816(sacc[2*jp],   al, khf[0], khf[1]);
                mma16816(sacc[2*jp+1], al, khf[2], khf[3]);
            }
        }

        // ---- issue second half of K(t+1) loads ----
        float2 kregB[9];
        #pragma unroll
        for (int it = 8; it < 16; ++it) {
            int idx = it * NTHREADS + tid;
            kregB[it - 8] = kmv2n[(idx >> 6) * 64 + (idx & 63)];
        }
        {
            int idx = NTHREADS + tid;
            kregB[8] = ks2n[(idx >> 3) * 8 + (idx & 7)];
        }

        // ---- softmax (bare ex2, scale pre-folded); P -> fp16 hi/lo fragments ----
        uint32_t Ph[4][4], Pl[4][4];
        float rst0 = 0.0f, rst1 = 0.0f;
        #pragma unroll
        for (int j = 0; j < 8; ++j) {
            float e0 = ex2f(sacc[j][0]);
            float e1 = ex2f(sacc[j][1]);
            float e2 = ex2f(sacc[j][2]);
            float e3 = ex2f(sacc[j][3]);
            rst0 += e0 + e1;
            rst1 += e2 + e3;
            const int kc = j >> 1, hh = (j & 1) * 2;
            Ph[kc][hh + 0] = pack_split(e0, e1, Pl[kc][hh + 0]);
            Ph[kc][hh + 1] = pack_split(e2, e3, Pl[kc][hh + 1]);
        }
        rst0 += __shfl_xor_sync(0xffffffffu, rst0, 1);
        rst0 += __shfl_xor_sync(0xffffffffu, rst0, 2);
        rst1 += __shfl_xor_sync(0xffffffffu, rst1, 1);
        rst1 += __shfl_xor_sync(0xffffffffu, rst1, 2);
        rs0a += rst0;
        rs1a += rst1;

        // ---- issue first half of V(t+1) loads ----
        float2 vregA[9];
        #pragma unroll
        for (int it = 0; it < 8; ++it) {
            int idx = it * NTHREADS + tid;
            vregA[it] = vmv2n[(idx >> 6) * 64 + (idx & 63)];
        }
        vregA[8] = vs2n[(tid >> 3) * 8 + (tid & 7)];

        // ---- convert+store K(t+1) into alternate buffer ----
        #pragma unroll
        for (int it = 0; it < 8; ++it) {
            int idx = it * NTHREADS + tid;
            int r = idx >> 6, w = idx & 63;
            uint32_t lo, hi = pack_split(kregA[it].x, kregA[it].y, lo);
            smw[nK + r * QW + w] = hi;
            smw[nK + KPL + r * QW + w] = lo;
        }
        {
            int r = tid >> 3, w = tid & 7;
            uint32_t lo, hi = pack_split(kregA[8].x, kregA[8].y, lo);
            smw[nK + r * QW + 64 + w] = hi;
            smw[nK + KPL + r * QW + 64 + w] = lo;
        }
        #pragma unroll
        for (int it = 8; it < 16; ++it) {
            int idx = it * NTHREADS + tid;
            int r = idx >> 6, w = idx & 63;
            uint32_t lo, hi = pack_split(kregB[it - 8].x, kregB[it - 8].y, lo);
            smw[nK + r * QW + w] = hi;
            smw[nK + KPL + r * QW + w] = lo;
        }
        {
            int idx = NTHREADS + tid;
            int r = idx >> 3, w = idx & 7;
            uint32_t lo, hi = pack_split(kregB[8].x, kregB[8].y, lo);
            smw[nK + r * QW + 64 + w] = hi;
            smw[nK + KPL + r * QW + 64 + w] = lo;
        }

        // ---- issue second half of V(t+1) loads ----
        float2 vregB[9];
        #pragma unroll
        for (int it = 8; it < 16; ++it) {
            int idx = it * NTHREADS + tid;
            vregB[it - 8] = vmv2n[(idx >> 6) * 64 + (idx & 63)];
        }
        {
            int idx = NTHREADS + tid;
            vregB[8] = vs2n[(idx >> 3) * 8 + (idx & 7)];
        }

        // ---- O += P V (2-term: (Ph+Pl) x Vh), V B-frags via ldmatrix.trans ----
        #pragma unroll 1
        for (int jp = 0; jp < 9; ++jp) {
            #pragma unroll
            for (int kc = 0; kc < 4; ++kc) {
                uint32_t vh[4];
                const uint32_t va = vbase + vb_lane
                                  + 4u * ((uint32_t)kc * 16u * QW + (uint32_t)jp * 8u);
                ldm4t(vh, va);
                mma16816(oacc[2*jp],   Ph[kc], vh[0], vh[1]);
                mma16816(oacc[2*jp+1], Ph[kc], vh[2], vh[3]);
                mma16816(oacc[2*jp],   Pl[kc], vh[0], vh[1]);
                mma16816(oacc[2*jp+1], Pl[kc], vh[2], vh[3]);
            }
        }

        // ---- convert+store V(t+1) into alternate buffer ----
        #pragma unroll
        for (int it = 0; it < 8; ++it) {
            int idx = it * NTHREADS + tid;
            int r = idx >> 6, w = idx & 63;
            smw[nV + r * QW + w] = pack_hi(vregA[it].x, vregA[it].y);
        }
        {
            int r = tid >> 3, w = tid & 7;
            smw[nV + r * QW + 64 + w] = pack_hi(vregA[8].x, vregA[8].y);
        }
        #pragma unroll
        for (int it = 8; it < 16; ++it) {
            int idx = it * NTHREADS + tid;
            int r = idx >> 6, w = idx & 63;
            smw[nV + r * QW + w] = pack_hi(vregB[it - 8].x, vregB[it - 8].y);
        }
        {
            int idx = NTHREADS + tid;
            int r = idx >> 3, w = idx & 7;
            smw[nV + r * QW + 64 + w] = pack_hi(vregB[8].x, vregB[8].y);
        }

        __syncthreads();
    }

    // ---------------- Epilogue: normalize + write ----------------
    {
        const int q4 = lane & 3;
        const float inv0 = 1.0f / rs0a;
        const float inv1 = 1.0f / rs1a;
        const size_t g0 = (size_t)(bh * SEQ + i0 + mrow + quad);
        const size_t g1 = g0 + 8;
        float* out_s = out + (size_t)BH * SEQ * DMV;
        #pragma unroll
        for (int j2 = 0; j2 < 18; ++j2) {
            const int col = j2 * 8 + q4 * 2;
            float2 r0 = make_float2(oacc[j2][0] * inv0, oacc[j2][1] * inv0);
            float2 r1 = make_float2(oacc[j2][2] * inv1, oacc[j2][3] * inv1);
            if (col < DMV) {
                *(float2*)(out + g0 * DMV + col) = r0;
                *(float2*)(out + g1 * DMV + col) = r1;
            } else {
                *(float2*)(out_s + g0 * DS + (col - DMV)) = r0;
                *(float2*)(out_s + g1 * DS + (col - DMV)) = r1;
            }
        }
    }
}

extern "C" void kernel_launch(void* const* d_in, const int* in_sizes, int n_in,
                              void* d_out, int out_size)
{
    (void)in_sizes; (void)n_in; (void)out_size;
    const float* q_mv = (const float*)d_in[0];
    const float* k_mv = (const float*)d_in[1];
    const float* v_mv = (const float*)d_in[2];
    const float* q_s  = (const float*)d_in[3];
    const float* k_s  = (const float*)d_in[4];
    const float* v_s  = (const float*)d_in[5];
    float* out = (float*)d_out;

    const int smem_bytes = SMEM_WORDS * 4;
    cudaFuncSetAttribute(geo_attn_hmma,
                         cudaFuncAttributeMaxDynamicSharedMemorySize, smem_bytes);
    dim3 grid(SEQ / BM, BH);
    geo_attn_hmma<<<grid, NTHREADS, smem_bytes>>>(q_mv, k_mv, v_mv, q_s, k_s, v_s, out);
}

// round 15
// speedup vs baseline: 1.2032x; 1.0289x over previous
#include <cuda_runtime.h>
#include <cuda_fp16.h>
#include <stdint.h>

#define BH      32
#define SEQ     2048
#define DMV     128
#define DS      16
#define DTOT    144
#define BM      128
#define BN      64
#define NTILES  (SEQ / BN)
#define NTHREADS 256
#define NROWS   (BH * SEQ)          // 65536
#define WPR     72                  // fp16x2 words per row (144 halves)

// SMEM word (u32) offsets — identical to R11 layout
#define QW     76
#define KPL    (BN * QW)            // 4864 words
#define O_QH   0
#define O_QL   (O_QH + BM * QW)     // 9728
#define O_K0   (O_QL + BM * QW)     // 19456 (hi plane; lo at +KPL)
#define O_K1   (O_K0 + 2 * KPL)     // 29184
#define O_V0   (O_K1 + 2 * KPL)     // 38912 (hi only)
#define O_V1   (O_V0 + KPL)         // 43776
#define SMEM_WORDS (O_V1 + KPL)     // 48640 words = 194560 B

#define NEGMASK 0xC0FCu             // -1 at indices {2..7,14,15} (mod 16)

// ---------------- preconverted fp16 planes (static device scratch) ----------------
__device__ __align__(16) uint32_t g_qh[NROWS * WPR];
__device__ __align__(16) uint32_t g_ql[NROWS * WPR];
__device__ __align__(16) uint32_t g_kh[NROWS * WPR];
__device__ __align__(16) uint32_t g_kl[NROWS * WPR];
__device__ __align__(16) uint32_t g_vh[NROWS * WPR];

static __device__ __forceinline__ uint32_t smem_u32(const void* p) {
    uint32_t a;
    asm("{ .reg .u64 t; cvta.to.shared.u64 t, %1; cvt.u32.u64 %0, t; }" : "=r"(a) : "l"(p));
    return a;
}

static __device__ __forceinline__ uint32_t pack_split(float x0, float x1, uint32_t& lop) {
    __half h0 = __float2half_rn(x0);
    __half h1 = __float2half_rn(x1);
    float r0 = x0 - __half2float(h0);
    float r1 = x1 - __half2float(h1);
    __half l0 = __float2half_rn(r0);
    __half l1 = __float2half_rn(r1);
    lop = (uint32_t)__half_as_ushort(l0) | ((uint32_t)__half_as_ushort(l1) << 16);
    return (uint32_t)__half_as_ushort(h0) | ((uint32_t)__half_as_ushort(h1) << 16);
}

static __device__ __forceinline__ uint32_t pack_hi(float x0, float x1) {
    __half2 h = __floats2half2_rn(x0, x1);
    return *(const uint32_t*)&h;
}

static __device__ __forceinline__ float ex2f(float x) {
    float r;
    asm("ex2.approx.f32 %0, %1;" : "=f"(r) : "f"(x));
    return r;
}

static __device__ __forceinline__ void mma16816(float* d, const uint32_t* a,
                                                uint32_t b0, uint32_t b1) {
    asm volatile(
        "mma.sync.aligned.m16n8k16.row.col.f32.f16.f16.f32 "
        "{%0,%1,%2,%3}, {%4,%5,%6,%7}, {%8,%9}, {%0,%1,%2,%3};"
        : "+f"(d[0]), "+f"(d[1]), "+f"(d[2]), "+f"(d[3])
        : "r"(a[0]), "r"(a[1]), "r"(a[2]), "r"(a[3]), "r"(b0), "r"(b1));
}

static __device__ __forceinline__ void ldm4(uint32_t* r, uint32_t saddr) {
    asm volatile("ldmatrix.sync.aligned.m8n8.x4.shared.b16 {%0,%1,%2,%3}, [%4];"
        : "=r"(r[0]), "=r"(r[1]), "=r"(r[2]), "=r"(r[3]) : "r"(saddr));
}

static __device__ __forceinline__ void ldm4t(uint32_t* r, uint32_t saddr) {
    asm volatile("ldmatrix.sync.aligned.m8n8.x4.trans.shared.b16 {%0,%1,%2,%3}, [%4];"
        : "=r"(r[0]), "=r"(r[1]), "=r"(r[2]), "=r"(r[3]) : "r"(saddr));
}

static __device__ __forceinline__ void cp16(uint32_t dst, const uint32_t* src) {
    asm volatile("cp.async.ca.shared.global [%0], [%1], 16;" :: "r"(dst), "l"(src));
}
#define CP_COMMIT() asm volatile("cp.async.commit_group;" ::: "memory")
#define CP_WAIT0()  asm volatile("cp.async.wait_group 0;" ::: "memory")

// ================= prepro: fp32 -> fp16 planes =================
__global__ __launch_bounds__(256)
void prepro_kernel(const float* __restrict__ q_mv, const float* __restrict__ k_mv,
                   const float* __restrict__ v_mv, const float* __restrict__ q_s,
                   const float* __restrict__ k_s,  const float* __restrict__ v_s)
{
    const float SCALE = 0.120224586740747f;   // log2(e)/12 folded into Q
    const int total = NROWS * WPR;
    for (int idx = blockIdx.x * 256 + threadIdx.x; idx < total; idx += gridDim.x * 256) {
        const int row = idx / WPR;
        const int w   = idx - row * WPR;
        float2 q, k, v;
        if (w < 64) {
            q = ((const float2*)q_mv)[(size_t)row * 64 + w];
            k = ((const float2*)k_mv)[(size_t)row * 64 + w];
            v = ((const float2*)v_mv)[(size_t)row * 64 + w];
            uint32_t fx = __float_as_uint(q.x) ^ (((NEGMASK >> ((2 * w) & 15)) & 1u) << 31);
            uint32_t fy = __float_as_uint(q.y) ^ (((NEGMASK >> ((2 * w + 1) & 15)) & 1u) << 31);
            q.x = __uint_as_float(fx);
            q.y = __uint_as_float(fy);
        } else {
            const int w2 = w - 64;
            q = ((const float2*)q_s)[(size_t)row * 8 + w2];
            k = ((const float2*)k_s)[(size_t)row * 8 + w2];
            v = ((const float2*)v_s)[(size_t)row * 8 + w2];
        }
        uint32_t lo, hi;
        hi = pack_split(q.x * SCALE, q.y * SCALE, lo);
        g_qh[idx] = hi;  g_ql[idx] = lo;
        hi = pack_split(k.x, k.y, lo);
        g_kh[idx] = hi;  g_kl[idx] = lo;
        g_vh[idx] = pack_hi(v.x, v.y);
    }
}

// ================= main attention kernel =================
__global__ __launch_bounds__(NTHREADS, 1)
void geo_attn_hmma(float* __restrict__ out)
{
    extern __shared__ uint32_t smw[];
    const uint32_t sb = smem_u32(smw);

    const int tid  = threadIdx.x;
    const int lane = tid & 31;
    const int wid  = tid >> 5;
    const int quad = lane >> 2;
    const int mrow = wid * 16;
    const int bh   = blockIdx.y;
    const int i0   = blockIdx.x * BM;

    const int l8  = lane & 7;
    const int lb3 = (lane >> 3) & 1;
    const int lb4 = (lane >> 4) & 1;
    const uint32_t qa_base = sb + 4u * (O_QH + (uint32_t)(mrow + lb3 * 8 + l8) * QW + lb4 * 4);
    const uint32_t kb_lane = 4u * ((uint32_t)(lb4 * 8 + l8) * QW + lb3 * 4);  // K (non-trans B)
    const uint32_t vb_lane = 4u * ((uint32_t)(lb3 * 8 + l8) * QW + lb4 * 4);  // V (trans B)

    // ---- prologue: Q (both planes) + K/V tile 0 via cp.async ----
    {
        const int qrow = bh * SEQ + i0;
        for (int i = tid; i < BM * (WPR / 4); i += NTHREADS) {   // 2304 chunks/plane
            const int r = i / 18, c4 = (i - r * 18) * 4;
            const uint32_t d = sb + 4u * (uint32_t)(r * QW + c4);
            const size_t s = (size_t)(qrow + r) * WPR + c4;
            cp16(d + 4u * O_QH, &g_qh[s]);
            cp16(d + 4u * O_QL, &g_ql[s]);
        }
        const int krow = bh * SEQ;
        for (int i = tid; i < BN * (WPR / 4); i += NTHREADS) {   // 1152 chunks/plane
            const int r = i / 18, c4 = (i - r * 18) * 4;
            const uint32_t d = sb + 4u * (uint32_t)(r * QW + c4);
            const size_t s = (size_t)(krow + r) * WPR + c4;
            cp16(d + 4u * O_K0, &g_kh[s]);
            cp16(d + 4u * (O_K0 + KPL), &g_kl[s]);
            cp16(d + 4u * O_V0, &g_vh[s]);
        }
        CP_COMMIT();
        CP_WAIT0();
    }
    __syncthreads();

    float oacc[18][4];
    #pragma unroll
    for (int j = 0; j < 18; ++j)
        #pragma unroll
        for (int r = 0; r < 4; ++r) oacc[j][r] = 0.0f;
    float rs0a = 0.0f, rs1a = 0.0f;

    for (int t = 0; t < NTILES; ++t) {
        const int buf = t & 1;
        const uint32_t kbase = sb + 4u * (uint32_t)(O_K0 + buf * (2 * KPL));
        const uint32_t vbase = sb + 4u * (uint32_t)(O_V0 + buf * KPL);
        const int nK = O_K0 + (buf ^ 1) * (2 * KPL);
        const int nV = O_V0 + (buf ^ 1) * KPL;
        const int tn = (t + 1) & (NTILES - 1);

        // ---- issue cp.async for K/V(t+1) into alt buffer (window = whole tile) ----
        {
            const int krow = bh * SEQ + tn * BN;
            for (int i = tid; i < BN * (WPR / 4); i += NTHREADS) {
                const int r = i / 18, c4 = (i - r * 18) * 4;
                const uint32_t d = sb + 4u * (uint32_t)(r * QW + c4);
                const size_t s = (size_t)(krow + r) * WPR + c4;
                cp16(d + 4u * (uint32_t)nK, &g_kh[s]);
                cp16(d + 4u * (uint32_t)(nK + KPL), &g_kl[s]);
                cp16(d + 4u * (uint32_t)nV, &g_vh[s]);
            }
            CP_COMMIT();
        }

        // ---- S = Q K^T (3-term split) ----
        float sacc[8][4];
        #pragma unroll
        for (int j = 0; j < 8; ++j)
            #pragma unroll
            for (int r = 0; r < 4; ++r) sacc[j][r] = 0.0f;

        #pragma unroll 1
        for (int c = 0; c < 9; ++c) {
            uint32_t ah[4], al[4];
            const uint32_t qa = qa_base + (uint32_t)c * 32u;
            ldm4(ah, qa);
            ldm4(al, qa + 4u * (uint32_t)(O_QL - O_QH));
            #pragma unroll
            for (int jp = 0; jp < 4; ++jp) {
                uint32_t khf[4], klf[4];
                const uint32_t ka = kbase + (uint32_t)jp * (16u * QW * 4u)
                                  + (uint32_t)c * 32u + kb_lane;
                ldm4(khf, ka);
                ldm4(klf, ka + 4u * (uint32_t)KPL);
                mma16816(sacc[2*jp],   ah, khf[0], khf[1]);
                mma16816(sacc[2*jp+1], ah, khf[2], khf[3]);
                mma16816(sacc[2*jp],   ah, klf[0], klf[1]);
                mma16816(sacc[2*jp+1], ah, klf[2], klf[3]);
                mma16816(sacc[2*jp],   al, khf[0], khf[1]);
                mma16816(sacc[2*jp+1], al, khf[2], khf[3]);
            }
        }

        // ---- softmax (bare ex2; scale pre-folded in prepro) ----
        uint32_t Ph[4][4], Pl[4][4];
        float rst0 = 0.0f, rst1 = 0.0f;
        #pragma unroll
        for (int j = 0; j < 8; ++j) {
            float e0 = ex2f(sacc[j][0]);
            float e1 = ex2f(sacc[j][1]);
            float e2 = ex2f(sacc[j][2]);
            float e3 = ex2f(sacc[j][3]);
            rst0 += e0 + e1;
            rst1 += e2 + e3;
            const int kc = j >> 1, hh = (j & 1) * 2;
            Ph[kc][hh + 0] = pack_split(e0, e1, Pl[kc][hh + 0]);
            Ph[kc][hh + 1] = pack_split(e2, e3, Pl[kc][hh + 1]);
        }
        rst0 += __shfl_xor_sync(0xffffffffu, rst0, 1);
        rst0 += __shfl_xor_sync(0xffffffffu, rst0, 2);
        rst1 += __shfl_xor_sync(0xffffffffu, rst1, 1);
        rst1 += __shfl_xor_sync(0xffffffffu, rst1, 2);
        rs0a += rst0;
        rs1a += rst1;

        // ---- O += P V (2-term: (Ph+Pl) x Vh), V B-frags via ldmatrix.trans ----
        #pragma unroll 1
        for (int jp = 0; jp < 9; ++jp) {
            #pragma unroll
            for (int kc = 0; kc < 4; ++kc) {
                uint32_t vh[4];
                const uint32_t va = vbase + vb_lane
                                  + 4u * ((uint32_t)kc * 16u * QW + (uint32_t)jp * 8u);
                ldm4t(vh, va);
                mma16816(oacc[2*jp],   Ph[kc], vh[0], vh[1]);
                mma16816(oacc[2*jp+1], Ph[kc], vh[2], vh[3]);
                mma16816(oacc[2*jp],   Pl[kc], vh[0], vh[1]);
                mma16816(oacc[2*jp+1], Pl[kc], vh[2], vh[3]);
            }
        }

        // ---- drain copies for t+1, then flip buffers ----
        CP_WAIT0();
        __syncthreads();
    }

    // ---------------- Epilogue: normalize + write ----------------
    {
        const int q4 = lane & 3;
        const float inv0 = 1.0f / rs0a;
        const float inv1 = 1.0f / rs1a;
        const size_t g0 = (size_t)(bh * SEQ + i0 + mrow + quad);
        const size_t g1 = g0 + 8;
        float* out_s = out + (size_t)BH * SEQ * DMV;
        #pragma unroll
        for (int j2 = 0; j2 < 18; ++j2) {
            const int col = j2 * 8 + q4 * 2;
            float2 r0 = make_float2(oacc[j2][0] * inv0, oacc[j2][1] * inv0);
            float2 r1 = make_float2(oacc[j2][2] * inv1, oacc[j2][3] * inv1);
            if (col < DMV) {
                *(float2*)(out + g0 * DMV + col) = r0;
                *(float2*)(out + g1 * DMV + col) = r1;
            } else {
                *(float2*)(out_s + g0 * DS + (col - DMV)) = r0;
                *(float2*)(out_s + g1 * DS + (col - DMV)) = r1;
            }
        }
    }
}

extern "C" void kernel_launch(void* const* d_in, const int* in_sizes, int n_in,
                              void* d_out, int out_size)
{
    (void)in_sizes; (void)n_in; (void)out_size;
    const float* q_mv = (const float*)d_in[0];
    const float* k_mv = (const float*)d_in[1];
    const float* v_mv = (const float*)d_in[2];
    const float* q_s  = (const float*)d_in[3];
    const float* k_s  = (const float*)d_in[4];
    const float* v_s  = (const float*)d_in[5];
    float* out = (float*)d_out;

    prepro_kernel<<<4096, 256>>>(q_mv, k_mv, v_mv, q_s, k_s, v_s);

    const int smem_bytes = SMEM_WORDS * 4;
    cudaFuncSetAttribute(geo_attn_hmma,
                         cudaFuncAttributeMaxDynamicSharedMemorySize, smem_bytes);
    dim3 grid(SEQ / BM, BH);
    geo_attn_hmma<<<grid, NTHREADS, smem_bytes>>>(out);
}